// round 6
// baseline (speedup 1.0000x reference)
#include <cuda_runtime.h>

// DeconvDft2dLayer == per-row 512-pt circular deconvolution:
//   y[row,:] = ifft( M(k) * fft(x[row,:]) ),  M(k) = 1/|H(k)|^4 (real),
//   H(k) = sum_{n=0}^{7} w[n] e^{-2pi i k n/512}.
// Two real rows packed per complex FFT (M real => exact).
// Warp-per-FFT: 512 = 32 x 16. Stage1 FFT16 in regs + twiddle, ONE
// conflict-free smem transpose, stage2 FFT16 + shfl radix-2 combine.
// Inverse via conj trick mirrors the pipeline. 16 complex regs/thread.

#define NW 512
#define WARPS 4
#define THREADS (WARPS * 32)
#define REG 272                  // words per parity region (16*17); 272 % 32 == 16

__device__ float d_M[NW];        // M(k)/512  (ifft 1/N folded in)

__global__ void compute_M_kernel(const float* __restrict__ w) {
    int k = threadIdx.x;
    float hr = 0.0f, hi = 0.0f;
#pragma unroll
    for (int n = 0; n < 8; n++) {
        int t = (k * n) & (NW - 1);
        float s, c;
        sincospif(-(float)t * (2.0f / NW), &s, &c);
        hr = fmaf(w[n], c, hr);
        hi = fmaf(w[n], s, hi);
    }
    float p = hr * hr + hi * hi;
    d_M[k] = 1.0f / (p * p * (float)NW);
}

// cos/sin(2*pi*j/32), j = 0..15 (compile-time).
__device__ __forceinline__ constexpr float c32(int j) {
    switch (j) {
        case 0:  return 1.0f;
        case 1:  return 0.9807852804032304491f;
        case 2:  return 0.9238795325112867561f;
        case 3:  return 0.8314696123025452371f;
        case 4:  return 0.7071067811865475244f;
        case 5:  return 0.5555702330196022248f;
        case 6:  return 0.3826834323650897717f;
        case 7:  return 0.1950903220161282678f;
        case 8:  return 0.0f;
        case 9:  return -0.1950903220161282678f;
        case 10: return -0.3826834323650897717f;
        case 11: return -0.5555702330196022248f;
        case 12: return -0.7071067811865475244f;
        case 13: return -0.8314696123025452371f;
        case 14: return -0.9238795325112867561f;
        default: return -0.9807852804032304491f;
    }
}
__device__ __forceinline__ constexpr float s32(int j) {
    switch (j) {
        case 0:  return 0.0f;
        case 1:  return 0.1950903220161282678f;
        case 2:  return 0.3826834323650897717f;
        case 3:  return 0.5555702330196022248f;
        case 4:  return 0.7071067811865475244f;
        case 5:  return 0.8314696123025452371f;
        case 6:  return 0.9238795325112867561f;
        case 7:  return 0.9807852804032304491f;
        case 8:  return 1.0f;
        case 9:  return 0.9807852804032304491f;
        case 10: return 0.9238795325112867561f;
        case 11: return 0.8314696123025452371f;
        case 12: return 0.7071067811865475244f;
        case 13: return 0.5555702330196022248f;
        case 14: return 0.3826834323650897717f;
        default: return 0.1950903220161282678f;
    }
}

__device__ __forceinline__ constexpr int brev4(int p) {
    return ((p & 1) << 3) | ((p & 2) << 1) | ((p & 4) >> 1) | ((p & 8) >> 3);
}

// Radix-2 DIF FFT16: natural input, bit-reversed output (reg p = X[brev4(p)]).
__device__ __forceinline__ void fft16_dif(float* __restrict__ xr,
                                          float* __restrict__ xi) {
#pragma unroll
    for (int m = 8; m >= 1; m >>= 1) {
#pragma unroll
        for (int g = 0; g < 16; g += 2 * m) {
#pragma unroll
            for (int j = 0; j < m; j++) {
                int a = g + j, b = a + m;
                float ur = xr[a], ui = xi[a];
                float vr = xr[b], vi = xi[b];
                xr[a] = ur + vr;
                xi[a] = ui + vi;
                float dr = ur - vr, di = ui - vi;
                float wc = c32(j * 16 / m);     // W_{2m}^j
                float ws = s32(j * 16 / m);
                xr[b] = dr * wc + di * ws;      // (dr + i di)(wc - i ws)
                xi[b] = di * wc - dr * ws;
            }
        }
    }
}

// Radix-2 DIT FFT16: bit-reversed input (reg p = x[brev4(p)]), natural output.
__device__ __forceinline__ void fft16_dit(float* __restrict__ xr,
                                          float* __restrict__ xi) {
#pragma unroll
    for (int m = 1; m < 16; m <<= 1) {
#pragma unroll
        for (int g = 0; g < 16; g += 2 * m) {
#pragma unroll
            for (int j = 0; j < m; j++) {
                int a = g + j, b = a + m;
                float wc = c32(j * 16 / m);
                float ws = s32(j * 16 / m);
                float tr = xr[b] * wc + xi[b] * ws;
                float ti = xi[b] * wc - xr[b] * ws;
                xr[b] = xr[a] - tr;
                xi[b] = xi[a] - ti;
                xr[a] += tr;
                xi[a] += ti;
            }
        }
    }
}

__global__ void __launch_bounds__(THREADS, 8)
fft_conv_kernel(const float* __restrict__ x, float* __restrict__ out) {
    __shared__ float sRe[WARPS][2 * REG];
    __shared__ float sIm[WARPS][2 * REG];
    __shared__ float sM[NW + 16];        // padded: addr = k + 16*(k>>8)

    int tid = threadIdx.x;
    int w = tid >> 5;
    int t = tid & 31;
    int h = t >> 4;        // half within warp
    int c = t & 15;
    float* Re = sRe[w];
    float* Im = sIm[w];

    for (int i = tid; i < NW; i += THREADS)
        sM[i + ((i >> 8) << 4)] = d_M[i];
    __syncthreads();       // the only block-wide sync

    long long row0 = ((long long)blockIdx.x * WARPS + w) * 2;
    const float* x0 = x + row0 * NW;
    const float* x1 = x0 + NW;

    // Twiddle base: e^{-2pi i t/512} (forward stage1 and inverse final reuse it).
    float btr, bti;
    sincospif(-(float)t * (1.0f / 256.0f), &bti, &btr);

    float ar[16], ai[16];
#pragma unroll
    for (int n2 = 0; n2 < 16; n2++) {    // n = t + 32*n2
        ar[n2] = __ldg(x0 + t + 32 * n2);
        ai[n2] = __ldg(x1 + t + 32 * n2);
    }

    // ---- forward stage 1: FFT16 over n2; reg p = F_t[brev4(p)] ----
    fft16_dif(ar, ai);

    // twiddle by W512^{t*k2} (running product, natural k2) + transposed store:
    // region by n1 parity (t&1), row k2 (stride 17), col t>>1.
    {
        int base = (t & 1) * REG + (t >> 1);
        float pr = 1.0f, pi = 0.0f;
#pragma unroll
        for (int k2 = 0; k2 < 16; k2++) {
            if (k2) {
                float nr = pr * btr - pi * bti;
                float ni = pr * bti + pi * btr;
                pr = nr; pi = ni;
            }
            int pos = brev4(k2);
            Re[base + 17 * k2] = ar[pos] * pr - ai[pos] * pi;
            Im[base + 17 * k2] = ar[pos] * pi + ai[pos] * pr;
        }
    }
    __syncwarp();

    // ---- forward stage 2: thread (h,c): E (h=0) / O (h=1) for k2 = c ----
    float cr[16], ci[16];
    {
        int base = h * REG + c * 17;
#pragma unroll
        for (int u = 0; u < 16; u++) {
            cr[u] = Re[base + u];
            ci[u] = Im[base + u];
        }
    }
    __syncwarp();          // buffer reused below

    fft16_dif(cr, ci);     // reg p = E/O[brev4(p)]

    // O side: multiply by W32^{brev4(p)}; then bfly-16 combine:
    // h=0: X_lo = E + O~ ; h=1: X_hi = E - O~.
#pragma unroll
    for (int p = 0; p < 16; p++) {
        if (h) {
            const float wc = c32(brev4(p)), ws = s32(brev4(p));
            float nr = cr[p] * wc + ci[p] * ws;
            float ni = ci[p] * wc - cr[p] * ws;
            cr[p] = nr; ci[p] = ni;
        }
        float rr = __shfl_xor_sync(0xffffffffu, cr[p], 16);
        float ri = __shfl_xor_sync(0xffffffffu, ci[p], 16);
        cr[p] = h ? (rr - cr[p]) : (cr[p] + rr);
        ci[p] = h ? (ri - ci[p]) : (ci[p] + ri);
    }
    // Thread t holds X[k], k = c + 16*brev4(p) + 256*h.

    // ---- g = conj(M * X); inverse = forward-FFT of g (conj trick) ----
#pragma unroll
    for (int p = 0; p < 16; p++) {
        float m = sM[c + 16 * brev4(p) + REG * h];   // 256h + 16h pad
        cr[p] = cr[p] * m;
        ci[p] = -ci[p] * m;
    }

    // inverse stage 1 (DIF over k1 high bit, via bfly):
    // h=0: s = g_lo + g_hi ; h=1: d = (g_lo - g_hi) * W32^{brev4(p)}.
#pragma unroll
    for (int p = 0; p < 16; p++) {
        float rr = __shfl_xor_sync(0xffffffffu, cr[p], 16);
        float ri = __shfl_xor_sync(0xffffffffu, ci[p], 16);
        if (h) {
            float dr = rr - cr[p], di = ri - ci[p];
            const float wc = c32(brev4(p)), ws = s32(brev4(p));
            cr[p] = dr * wc + di * ws;
            ci[p] = di * wc - dr * ws;
        } else {
            cr[p] = cr[p] + rr;
            ci[p] = ci[p] + ri;
        }
    }

    fft16_dit(cr, ci);     // bitrev input -> natural nu; reg nu = T_c/U_c[nu]

    // ---- transpose 2: region by h, row nu (stride 17), col c ----
    {
        int base = h * REG + c;
#pragma unroll
        for (int nu = 0; nu < 16; nu++) {
            Re[base + 17 * nu] = cr[nu];
            Im[base + 17 * nu] = ci[nu];
        }
    }
    __syncwarp();

    // read: thread t handles r = n mod 32 = t: parity region t&1, row t>>1.
    {
        int base = (t & 1) * REG + (t >> 1) * 17;
#pragma unroll
        for (int c2 = 0; c2 < 16; c2++) {
            cr[c2] = Re[base + c2];
            ci[c2] = Im[base + c2];
        }
    }

    // final twiddle W512^{c2*t} (same base btr/bti), then FFT16 over c2.
    {
        float pr = 1.0f, pi = 0.0f;
#pragma unroll
        for (int c2 = 0; c2 < 16; c2++) {
            if (c2) {
                float nr = pr * btr - pi * bti;
                float ni = pr * bti + pi * btr;
                pr = nr; pi = ni;
            }
            float vr = cr[c2] * pr - ci[c2] * pi;
            float vi = cr[c2] * pi + ci[c2] * pr;
            cr[c2] = vr; ci[c2] = vi;
        }
    }
    fft16_dif(cr, ci);     // reg p = Ghat[n = t + 32*brev4(p)]

    // y = conj(Ghat) (1/512 in M): re -> row0, -im -> row1.
    float* o0 = out + row0 * NW;
    float* o1 = o0 + NW;
#pragma unroll
    for (int p = 0; p < 16; p++) {
        int n = t + 32 * brev4(p);
        o0[n] = cr[p];
        o1[n] = -ci[p];
    }
}

extern "C" void kernel_launch(void* const* d_in, const int* in_sizes, int n_in,
                              void* d_out, int out_size) {
    const float* x = (const float*)d_in[0];
    const float* w = (const float*)d_in[1];
    if (n_in >= 2 && in_sizes[0] < in_sizes[1]) {
        const float* t = x; x = w; w = t;
    }
    float* out = (float*)d_out;

    compute_M_kernel<<<1, NW>>>(w);

    int rows = out_size / NW;            // 16384
    int blocks = rows / (2 * WARPS);     // 2048 (8 rows per block)
    fft_conv_kernel<<<blocks, THREADS>>>(x, out);
}

// round 7
// speedup vs baseline: 1.0997x; 1.0997x over previous
#include <cuda_runtime.h>

// DeconvDft2dLayer == per-row 512-pt circular deconvolution:
//   y[row,:] = ifft( M(k) * fft(x[row,:]) ),  M(k) = 1/|H(k)|^4 (real),
//   H(k) = sum_{n=0}^{7} w[n] e^{-2pi i k n/512}.
// Two real rows packed per complex FFT (M real => exact). Each thread runs
// TWO independent FFTs (4 rows). Radix-8 Stockham, IN-PLACE padded smem
// (one 9KB buffer pair, read-all/sync/write-all), serial twiddle chains
// (low regs), M computed per-thread in registers (single kernel launch):
// H at bins u+64j is an 8-pt DFT of v[n] = w[n]*w1^n, w1 = e^{-2pi i u/512}.

#define NW 512
#define THREADS 64
#define PAD2 (NW + (NW >> 3))   // 576 float2 per FFT buffer

__device__ __forceinline__ float2 cmulf(float2 a, float2 b) {
    return make_float2(a.x * b.x - a.y * b.y, a.x * b.y + a.y * b.x);
}

// In-register radix-8 DFT, natural-order output (reg j = bin j).
template<bool INV>
__device__ __forceinline__ void dft8(float* ar, float* ai) {
    const float s = INV ? 1.0f : -1.0f;
    const float C = 0.70710678118654752440f;

    float e0r = ar[0] + ar[4], e0i = ai[0] + ai[4];
    float e1r = ar[0] - ar[4], e1i = ai[0] - ai[4];
    float e2r = ar[2] + ar[6], e2i = ai[2] + ai[6];
    float e3r = ar[2] - ar[6], e3i = ai[2] - ai[6];
    float E0r = e0r + e2r, E0i = e0i + e2i;
    float E2r = e0r - e2r, E2i = e0i - e2i;
    float E1r = e1r - s * e3i, E1i = e1i + s * e3r;
    float E3r = e1r + s * e3i, E3i = e1i - s * e3r;

    float o0r = ar[1] + ar[5], o0i = ai[1] + ai[5];
    float o1r = ar[1] - ar[5], o1i = ai[1] - ai[5];
    float o2r = ar[3] + ar[7], o2i = ai[3] + ai[7];
    float o3r = ar[3] - ar[7], o3i = ai[3] - ai[7];
    float O0r = o0r + o2r, O0i = o0i + o2i;
    float O2r = o0r - o2r, O2i = o0i - o2i;
    float O1r = o1r - s * o3i, O1i = o1i + s * o3r;
    float O3r = o1r + s * o3i, O3i = o1i - s * o3r;

    float w1r = C * (O1r - s * O1i), w1i = C * (s * O1r + O1i);
    float w2r = -s * O2i,             w2i = s * O2r;
    float w3r = C * (-O3r - s * O3i), w3i = C * (s * O3r - O3i);

    ar[0] = E0r + O0r; ai[0] = E0i + O0i;
    ar[4] = E0r - O0r; ai[4] = E0i - O0i;
    ar[1] = E1r + w1r; ai[1] = E1i + w1i;
    ar[5] = E1r - w1r; ai[5] = E1i - w1i;
    ar[2] = E2r + w2r; ai[2] = E2i + w2i;
    ar[6] = E2r - w2r; ai[6] = E2i - w2i;
    ar[3] = E3r + w3r; ai[3] = E3i + w3i;
    ar[7] = E3r - w3r; ai[7] = E3i - w3i;
}

// Twiddle both FFTs by W^j (conj for INV) and store; serial running-product
// power chain (1 live power pair) shared by A and B.
template<bool INV>
__device__ __forceinline__ void tw_store2(float2* __restrict__ bufA,
                                          float2* __restrict__ bufB,
                                          const float* ar, const float* ai,
                                          const float* br, const float* bi,
                                          float2 w, int base, int stride) {
    if (INV) w.y = -w.y;
    bufA[base] = make_float2(ar[0], ai[0]);
    bufB[base] = make_float2(br[0], bi[0]);
    float pr = w.x, pi = w.y;
#pragma unroll
    for (int j = 1; j < 8; j++) {
        int idx = base + stride * j;
        bufA[idx] = make_float2(ar[j] * pr - ai[j] * pi, ar[j] * pi + ai[j] * pr);
        bufB[idx] = make_float2(br[j] * pr - bi[j] * pi, br[j] * pi + bi[j] * pr);
        if (j < 7) {
            float nr = pr * w.x - pi * w.y;
            float ni = pr * w.y + pi * w.x;
            pr = nr; pi = ni;
        }
    }
}

__device__ __forceinline__ void load2(float* ar, float* ai, float* br, float* bi,
                                      const float2* __restrict__ bufA,
                                      const float2* __restrict__ bufB, int ub) {
#pragma unroll
    for (int j = 0; j < 8; j++) {
        float2 va = bufA[ub + 72 * j];
        float2 vb = bufB[ub + 72 * j];
        ar[j] = va.x; ai[j] = va.y;
        br[j] = vb.x; bi[j] = vb.y;
    }
}

__global__ void __launch_bounds__(THREADS, 16)
fft_conv_kernel(const float* __restrict__ x, const float* __restrict__ w,
                float* __restrict__ out) {
    __shared__ float2 S[2][PAD2];   // single in-place buffer pair (FFT A, FFT B)

    int u = threadIdx.x;
    int ub = u + (u >> 3);
    int p = u >> 3, q = u & 7;

    float2 w1, w2;
    sincospif(-(float)u * (1.0f / 256.0f), &w1.y, &w1.x);   // e^{-2pi i u/512}
    sincospif(-(float)p * (1.0f / 32.0f),  &w2.y, &w2.x);   // e^{-2pi i p/64}

    int base = blockIdx.x * (4 * NW);   // 4 rows per block, fits in int
    const float* xA0 = x + base;
    const float* xA1 = xA0 + NW;
    const float* xB0 = xA0 + 2 * NW;
    const float* xB1 = xA0 + 3 * NW;

    float ar[8], ai[8], br[8], bi[8];
#pragma unroll
    for (int j = 0; j < 8; j++) {
        int g = u + 64 * j;
        ar[j] = __ldg(xA0 + g);
        ai[j] = __ldg(xA1 + g);
        br[j] = __ldg(xB0 + g);
        bi[j] = __ldg(xB1 + g);
    }

    // ---- forward ----
    dft8<false>(ar, ai);
    dft8<false>(br, bi);
    tw_store2<false>(S[0], S[1], ar, ai, br, bi, w1, 9 * u, 1);
    __syncthreads();
    load2(ar, ai, br, bi, S[0], S[1], ub);
    __syncthreads();                    // all reads done before in-place overwrite

    dft8<false>(ar, ai);
    dft8<false>(br, bi);
    tw_store2<false>(S[0], S[1], ar, ai, br, bi, w2, q + 72 * p, 9);
    __syncthreads();
    load2(ar, ai, br, bi, S[0], S[1], ub);
    __syncthreads();

    dft8<false>(ar, ai);
    dft8<false>(br, bi);                // natural order: reg j = bin u+64j

    // ---- fused M: H(u+64j) = DFT8_j( w[n] * w1^n ),  M = 1/(|H|^2)^2 / 512 ----
    {
        float vr[8], vi[8];
        vr[0] = __ldg(w + 0);
        vi[0] = 0.0f;
        float pr = w1.x, pi = w1.y;
#pragma unroll
        for (int n = 1; n < 8; n++) {
            float wt = __ldg(w + n);
            vr[n] = wt * pr;
            vi[n] = wt * pi;
            if (n < 7) {
                float nr = pr * w1.x - pi * w1.y;
                float ni = pr * w1.y + pi * w1.x;
                pr = nr; pi = ni;
            }
        }
        dft8<false>(vr, vi);            // vr[j]+i vi[j] = H(u + 64j)
#pragma unroll
        for (int j = 0; j < 8; j++) {
            float pw = vr[j] * vr[j] + vi[j] * vi[j];    // |H|^2
            float m = 1.0f / (pw * pw * (float)NW);       // ifft 1/N folded in
            ar[j] *= m; ai[j] *= m;
            br[j] *= m; bi[j] *= m;
        }
    }

    // ---- inverse ----
    dft8<true>(ar, ai);
    dft8<true>(br, bi);
    tw_store2<true>(S[0], S[1], ar, ai, br, bi, w1, 9 * u, 1);
    __syncthreads();
    load2(ar, ai, br, bi, S[0], S[1], ub);
    __syncthreads();

    dft8<true>(ar, ai);
    dft8<true>(br, bi);
    tw_store2<true>(S[0], S[1], ar, ai, br, bi, w2, q + 72 * p, 9);
    __syncthreads();
    load2(ar, ai, br, bi, S[0], S[1], ub);

    dft8<true>(ar, ai);
    dft8<true>(br, bi);

    float* oA0 = out + base;
    float* oA1 = oA0 + NW;
    float* oB0 = oA0 + 2 * NW;
    float* oB1 = oA0 + 3 * NW;
#pragma unroll
    for (int j = 0; j < 8; j++) {
        int g = u + 64 * j;
        oA0[g] = ar[j];
        oA1[g] = ai[j];
        oB0[g] = br[j];
        oB1[g] = bi[j];
    }
}

extern "C" void kernel_launch(void* const* d_in, const int* in_sizes, int n_in,
                              void* d_out, int out_size) {
    const float* x = (const float*)d_in[0];
    const float* w = (const float*)d_in[1];
    if (n_in >= 2 && in_sizes[0] < in_sizes[1]) {   // defensive: x is the big one
        const float* t = x; x = w; w = t;
    }
    float* out = (float*)d_out;

    int rows = out_size / NW;        // 16384
    int blocks = rows / 4;           // 4096 (4 rows per block)
    fft_conv_kernel<<<blocks, THREADS>>>(x, w, out);
}